// round 13
// baseline (speedup 1.0000x reference)
#include <cuda_runtime.h>
#include <cstdint>

// 256 images, 512x512 fp32; per-image bilinear shift with mirror boundary.
// d_in[0] = images, d_in[1] = dxdy ([b][0]=dy, [b][1]=dx).
//
// Fully separable + constant-shift formulation:
//   fy = frac(y - dy)   (per-block constant, reference expression)
//   fx = frac(-dx), s = floor(-dx)   (per-IMAGE constants; for integer x,
//        floor(x - dx) = x + s and frac(x - dx) = fx exactly)
// Stage combined row c[PAD+g] = (1-fy)*row0[g] + fy*row1[g] with aligned
// STS.128 + 8-cell mirror halos; output row y as float4s:
//   out[4t..4t+3] = (1-fx)*c[off..off+3] + fx*c[off+1..off+4], off = PAD+s+4t
// via two aligned LDS.128 and a block-uniform lane-select switch on off&3.

#define H 512
#define W 512
#define PAD 8            // covers |dx| < 7; dx ~ N(0,1)

__device__ __forceinline__ int mirror_fast(int idx, int n) {
    int i = idx < 0 ? -idx : idx;
    return (i >= n) ? (2 * (n - 1) - i) : i;
}

__global__ __launch_bounds__(128)
void shift_bilinear_v5_kernel(const float* __restrict__ img,
                              const float* __restrict__ dxdy,
                              float* __restrict__ out) {
    __shared__ __align__(16) float c[PAD + W + PAD];   // 528 floats

    const int y = blockIdx.x;   // output row
    const int b = blockIdx.y;   // image
    const int t = threadIdx.x;

    const float2 d = __ldg((const float2*)dxdy + b);
    const float dy = d.x;
    const float dx = d.y;

    // Vertical constants (reference-exact)
    const float cy  = (float)y - dy;
    const float y0f = floorf(cy);
    const float fy  = cy - y0f;
    const int   y0  = (int)y0f;
    const int   y0m = mirror_fast(y0,     H);
    const int   y1m = mirror_fast(y0 + 1, H);
    const float wy0 = 1.0f - fy;

    // Horizontal constants (per-image)
    const float nfx = -dx;
    const float sf  = floorf(nfx);
    const float fx  = nfx - sf;          // frac(-dx)
    const int   s   = (int)sf;           // floor(-dx)
    const float wx0 = 1.0f - fx;

    const size_t img_base = (size_t)b * (H * W);
    const float* __restrict__ r0 = img + img_base + (size_t)y0m * W;
    const float* __restrict__ r1 = img + img_base + (size_t)y1m * W;

    // ---- Stage interior: one aligned STS.128 per thread ----
    {
        const float4 a  = __ldg((const float4*)r0 + t);
        const float4 bv = __ldg((const float4*)r1 + t);
        float4 v;
        v.x = fmaf(wy0, a.x, fy * bv.x);
        v.y = fmaf(wy0, a.y, fy * bv.y);
        v.z = fmaf(wy0, a.z, fy * bv.z);
        v.w = fmaf(wy0, a.w, fy * bv.w);
        ((float4*)(c + PAD))[t] = v;
    }

    // ---- Halos (16 cells, first half-warp) ----
    if (t < 16) {
        int k, g;
        if (t < 8) { k = t;               g = PAD - t; }          // left:  g=-8..-1 mirrored
        else       { k = PAD + W + (t-8); g = (W - 2) - (t - 8); }// right: g=512..519 mirrored
        c[k] = fmaf(wy0, __ldg(r0 + g), fy * __ldg(r1 + g));
    }
    __syncthreads();

    // ---- Output: 4 consecutive pixels per thread, 2 LDS.128 + 1 STG.128 ----
    const int off0 = PAD + s;            // >= 1 for s >= -7
    const int r    = off0 & 3;           // block-uniform misalignment
    const int f0   = (off0 >> 2) + t;    // aligned float4 index for this thread

    const float4 e0 = ((const float4*)c)[f0];
    const float4 e1 = ((const float4*)c)[f0 + 1];

    // Select the 5-value window w[0..4] = c[off0+4t .. off0+4t+4]
    float v0, v1, v2, v3, v4;
    switch (r) {
        case 0: v0=e0.x; v1=e0.y; v2=e0.z; v3=e0.w; v4=e1.x; break;
        case 1: v0=e0.y; v1=e0.z; v2=e0.w; v3=e1.x; v4=e1.y; break;
        case 2: v0=e0.z; v1=e0.w; v2=e1.x; v3=e1.y; v4=e1.z; break;
        default:v0=e0.w; v1=e1.x; v2=e1.y; v3=e1.z; v4=e1.w; break;
    }

    float4 o;
    o.x = fmaf(fx, v1, wx0 * v0);
    o.y = fmaf(fx, v2, wx0 * v1);
    o.z = fmaf(fx, v3, wx0 * v2);
    o.w = fmaf(fx, v4, wx0 * v3);

    ((float4*)(out + img_base + (size_t)y * W))[t] = o;
}

extern "C" void kernel_launch(void* const* d_in, const int* in_sizes, int n_in,
                              void* d_out, int out_size) {
    const float* images = (const float*)d_in[0];
    const float* dxdy   = (const float*)d_in[1];
    float* out = (float*)d_out;

    dim3 grid(H, 256, 1);
    dim3 block(128, 1, 1);
    shift_bilinear_v5_kernel<<<grid, block>>>(images, dxdy, out);
}

// round 14
// speedup vs baseline: 1.0710x; 1.0710x over previous
#include <cuda_runtime.h>
#include <cstdint>

// 256 images, 512x512 fp32; per-image bilinear shift with mirror boundary.
// d_in[0] = images, d_in[1] = dxdy ([b][0]=dy, [b][1]=dx).
//
// Fully-constant separable formulation:
//   s_y = floor(-dy), fy = frac(-dy); s_x = floor(-dx), fx = frac(-dx)
// (per-image constants; for integer y, floor(y - dy) = y + s_y etc.)
// A block handles R=4 consecutive output rows of one image:
//   - loads the R+1 = 5 shared source rows (mirrored) once, float4 per thread
//   - builds the 4 fy-combined rows in smem (aligned STS.128 + mirror halos)
//   - emits each output row from 2 aligned LDS.128 + 8 FMA + 1 STG.128,
//     with the shift handled by a block-uniform lane-select on (PAD+s_x)&3.

#define H 512
#define W 512
#define PAD 8                    // covers |dx|,|dy| < 7 (inputs are N(0,1))
#define R 4
#define STRIDE (PAD + W + PAD)   // 528 floats, 2112 B (16B-aligned rows)

__device__ __forceinline__ int mirror_fast(int idx, int n) {
    int i = idx < 0 ? -idx : idx;
    return (i >= n) ? (2 * (n - 1) - i) : i;
}

__global__ __launch_bounds__(128)
void shift_bilinear_v6_kernel(const float* __restrict__ img,
                              const float* __restrict__ dxdy,
                              float* __restrict__ out) {
    __shared__ __align__(16) float c[R][STRIDE];

    const int yb = blockIdx.x * R;   // first output row of this block
    const int b  = blockIdx.y;       // image
    const int t  = threadIdx.x;

    const float2 d = __ldg((const float2*)dxdy + b);
    const float dy = d.x;
    const float dx = d.y;

    // Per-image vertical constants
    const float nfy = -dy;
    const float syf = floorf(nfy);
    const float fy  = nfy - syf;
    const int   sy  = (int)syf;
    const float wy0 = 1.0f - fy;

    // Per-image horizontal constants
    const float nfx = -dx;
    const float sxf = floorf(nfx);
    const float fx  = nfx - sxf;
    const int   sx  = (int)sxf;
    const float wx0 = 1.0f - fx;

    const size_t img_base = (size_t)b * (H * W);

    // Mirrored source-row pointers (R+1 rows: yb+sy .. yb+sy+R)
    const float* __restrict__ rows[R + 1];
#pragma unroll
    for (int k = 0; k <= R; k++) {
        const int ry = mirror_fast(yb + sy + k, H);
        rows[k] = img + img_base + (size_t)ry * W;
    }

    // ---- Load all 5 source float4s (front-batched for MLP) ----
    float4 v[R + 1];
#pragma unroll
    for (int k = 0; k <= R; k++)
        v[k] = __ldg((const float4*)rows[k] + t);

    // ---- Combine vertically and store interior (aligned STS.128) ----
#pragma unroll
    for (int k = 0; k < R; k++) {
        float4 o;
        o.x = fmaf(wy0, v[k].x, fy * v[k + 1].x);
        o.y = fmaf(wy0, v[k].y, fy * v[k + 1].y);
        o.z = fmaf(wy0, v[k].z, fy * v[k + 1].z);
        o.w = fmaf(wy0, v[k].w, fy * v[k + 1].w);
        ((float4*)(c[k] + PAD))[t] = o;
    }

    // ---- Halos: 4 rows x 16 cells = 64, handled by threads 64..127 ----
    if (t >= 64) {
        const int idx = t - 64;       // 0..63
        const int k   = idx >> 4;     // combined row
        const int i   = idx & 15;     // halo cell
        int kk, g;
        if (i < 8) { kk = i;                 g = PAD - i;         } // left:  x=-8..-1 mirrored
        else       { kk = PAD + W + (i - 8); g = (W - 2) - (i - 8);} // right: x=512..519 mirrored
        c[k][kk] = fmaf(wy0, __ldg(rows[k] + g), fy * __ldg(rows[k + 1] + g));
    }
    __syncthreads();

    // ---- Output: per row, 2 aligned LDS.128 + lane-select + 8 FMA + STG.128 ----
    const int off0 = PAD + sx;            // in [1, 15]
    const int rsel = off0 & 3;            // block-uniform misalignment
    const int f0   = (off0 >> 2) + t;     // aligned float4 index

    float* __restrict__ obase = out + img_base + (size_t)yb * W;

#define EMIT_ROWS(SEL0, SEL1, SEL2, SEL3, SEL4)                                 \
    _Pragma("unroll")                                                           \
    for (int k = 0; k < R; k++) {                                               \
        const float4 e0 = ((const float4*)c[k])[f0];                            \
        const float4 e1 = ((const float4*)c[k])[f0 + 1];                        \
        const float w0 = SEL0, w1 = SEL1, w2 = SEL2, w3 = SEL3, w4 = SEL4;      \
        float4 o;                                                               \
        o.x = fmaf(fx, w1, wx0 * w0);                                           \
        o.y = fmaf(fx, w2, wx0 * w1);                                           \
        o.z = fmaf(fx, w3, wx0 * w2);                                           \
        o.w = fmaf(fx, w4, wx0 * w3);                                           \
        ((float4*)(obase + (size_t)k * W))[t] = o;                              \
    }

    switch (rsel) {
        case 0:  EMIT_ROWS(e0.x, e0.y, e0.z, e0.w, e1.x); break;
        case 1:  EMIT_ROWS(e0.y, e0.z, e0.w, e1.x, e1.y); break;
        case 2:  EMIT_ROWS(e0.z, e0.w, e1.x, e1.y, e1.z); break;
        default: EMIT_ROWS(e0.w, e1.x, e1.y, e1.z, e1.w); break;
    }
#undef EMIT_ROWS
}

extern "C" void kernel_launch(void* const* d_in, const int* in_sizes, int n_in,
                              void* d_out, int out_size) {
    const float* images = (const float*)d_in[0];
    const float* dxdy   = (const float*)d_in[1];
    float* out = (float*)d_out;

    dim3 grid(H / R, 256, 1);   // 128 x 256 blocks
    dim3 block(128, 1, 1);
    shift_bilinear_v6_kernel<<<grid, block>>>(images, dxdy, out);
}